// round 13
// baseline (speedup 1.0000x reference)
#include <cuda_runtime.h>
#include <cstdint>

// Problem constants (fixed shapes per reference)
#define NB      32
#define NC      64
#define NIN     10475
#define NOUT    2619
#define NNZ     (8 * NOUT)        // 20952
#define GPAIR   4                 // (b,c) pairs per block
#define NPAIR   (NB * NC)         // 2048
#define NBLK    (NPAIR / GPAIR)   // 512
#define THREADS 1024
#define ROWS_PT 3                 // ceil(NOUT / THREADS)
#define MAXSLOT 32                // Poisson(4)/half-row; overflow ~0, guarded
#define HALF    5238              // column split point (ceil(NIN/2))
#define SMCOLS  5240              // padded float4 granules per half
#define SMEM_BYTES (SMCOLS * sizeof(float4))  // 83,840 B -> 2 CTAs/SM

// Device scratch (zero-init at load; no runtime allocation)
__device__ int      d_cntL[NOUT];             // per-half counts; reset each call
__device__ int      d_cntH[NOUT];
__device__ int2     d_entL[MAXSLOT * NOUT];   // slot-major {local col, val-bits}
__device__ int2     d_entH[MAXSLOT * NOUT];
__device__ unsigned d_done;

// ---------------- ELL fill, bucketed by column half ----------------
__global__ void k_fill(const int* __restrict__ rows,
                       const int* __restrict__ cols,
                       const float* __restrict__ vals) {
    int k = blockIdx.x * blockDim.x + threadIdx.x;
    if (k < NNZ) {
        int r = rows[k];
        int c = cols[k];
        int vb = __float_as_int(vals[k]);
        if (c < HALF) {
            int slot = atomicAdd(&d_cntL[r], 1);
            if (slot < MAXSLOT) d_entL[slot * NOUT + r] = make_int2(c, vb);
        } else {
            int slot = atomicAdd(&d_cntH[r], 1);
            if (slot < MAXSLOT) d_entH[slot * NOUT + r] = make_int2(c - HALF, vb);
        }
    }
}

// ---------------- Main SpMM kernel ----------------
// Round-8 structure (GPAIR=4, two column-half phases, 2 CTAs/SM) but with
// 1024 threads and a 32-reg budget -> 64 warps/SM (full occupancy), which
// attacks the latency-exposure profile directly. Gather stays float4-
// interleaved: one LDS.128 per entry serves all 4 pairs. 3 lockstep
// row-chains per thread; accumulators persist across halves.
__global__ __launch_bounds__(THREADS, 2)
void k_main(const float* __restrict__ x, float* __restrict__ out) {
    extern __shared__ float4 sm4[];   // SMCOLS granules
    const int tid = threadIdx.x;
    const int pb  = blockIdx.x * GPAIR;

    float4 acc[ROWS_PT];
    #pragma unroll
    for (int i = 0; i < ROWS_PT; i++) acc[i] = make_float4(0.f, 0.f, 0.f, 0.f);

    #pragma unroll
    for (int h = 0; h < 2; h++) {
        const int ncols = h ? (NIN - HALF) : HALF;
        const float* __restrict__ xh = x + (size_t)pb * NIN + h * HALF;

        // ---- stage this column half: 4 coalesced streams -> STS.128 ----
        for (int j = tid; j < ncols; j += THREADS) {
            sm4[j] = make_float4(__ldg(xh + j),
                                 __ldg(xh + j + NIN),
                                 __ldg(xh + j + 2 * NIN),
                                 __ldg(xh + j + 3 * NIN));
        }
        __syncthreads();

        // ---- accumulate this half's entries: 3 lockstep row-chains ----
        const int*  __restrict__ cnt = h ? d_cntH : d_cntL;
        const int2* __restrict__ tbl = h ? d_entH : d_entL;

        int c[ROWS_PT];
        int cmax = 0;
        #pragma unroll
        for (int i = 0; i < ROWS_PT; i++) {
            int r = tid + i * THREADS;
            c[i] = (r < NOUT) ? min(cnt[r], MAXSLOT) : 0;
            cmax = max(cmax, c[i]);
        }

        for (int k = 0; k < cmax; k++) {
            const int2* __restrict__ ek = tbl + k * NOUT;
            #pragma unroll
            for (int i = 0; i < ROWS_PT; i++) {
                if (k < c[i]) {
                    int2 e = __ldg(ek + tid + i * THREADS);
                    float v  = __int_as_float(e.y);
                    float4 xv = sm4[e.x];
                    acc[i].x = fmaf(v, xv.x, acc[i].x);
                    acc[i].y = fmaf(v, xv.y, acc[i].y);
                    acc[i].z = fmaf(v, xv.z, acc[i].z);
                    acc[i].w = fmaf(v, xv.w, acc[i].w);
                }
            }
        }
        __syncthreads();   // smem reused by next half
    }

    // ---- coalesced stores: 4 output streams x 3 rows ----
    float* __restrict__ o0 = out + (size_t)pb * NOUT;
    #pragma unroll
    for (int i = 0; i < ROWS_PT; i++) {
        int r = tid + i * THREADS;
        if (r < NOUT) {
            o0[r]            = acc[i].x;
            o0[NOUT + r]     = acc[i].y;
            o0[2 * NOUT + r] = acc[i].z;
            o0[3 * NOUT + r] = acc[i].w;
        }
    }

    // ---- last finished block resets counts for the next graph replay ----
    __shared__ unsigned s_last;
    if (tid == 0) {
        __threadfence();
        s_last = (atomicAdd(&d_done, 1u) == (unsigned)(gridDim.x - 1));
    }
    __syncthreads();
    if (s_last) {
        for (int i = tid; i < NOUT; i += THREADS) { d_cntL[i] = 0; d_cntH[i] = 0; }
        if (tid == 0) d_done = 0;
    }
}

// ---------------- launch ----------------
extern "C" void kernel_launch(void* const* d_in, const int* in_sizes, int n_in,
                              void* d_out, int out_size) {
    const float* x      = (const float*)d_in[0];
    const int*   M_rows = (const int*)d_in[1];
    const int*   M_cols = (const int*)d_in[2];
    const float* M_vals = (const float*)d_in[3];
    float* out = (float*)d_out;

    (void)in_sizes; (void)n_in; (void)out_size;

    cudaFuncSetAttribute(k_main, cudaFuncAttributeMaxDynamicSharedMemorySize,
                         (int)SMEM_BYTES);

    k_fill<<<(NNZ + 255) / 256, 256>>>(M_rows, M_cols, M_vals);
    k_main<<<NBLK, THREADS, SMEM_BYTES>>>(x, out);
}

// round 14
// speedup vs baseline: 1.6459x; 1.6459x over previous
#include <cuda_runtime.h>
#include <cstdint>

// Problem constants (fixed shapes per reference)
#define NB      32
#define NC      64
#define NIN     10475
#define NOUT    2619
#define NNZ     (8 * NOUT)        // 20952
#define GPAIR   4                 // (b,c) pairs per block
#define NPAIR   (NB * NC)         // 2048
#define NBLK    (NPAIR / GPAIR)   // 512
#define THREADS 512
#define ROWS_PT 6                 // ceil(NOUT / THREADS)
#define MAXSLOT 32                // Poisson(4)/half-row; overflow ~0, guarded
#define HALF    5238              // column split point (ceil(NIN/2))
#define SMCOLS  5240              // padded float4 granules per half
#define NSM     148               // SMs on GB300 (CTA pair on an SM = bid, bid+NSM)
#define SMEM_BYTES (SMCOLS * sizeof(float4))  // 83,840 B -> 2 CTAs/SM

// Device scratch (zero-init at load; no runtime allocation)
__device__ int      d_cntL[NOUT];             // per-half counts; reset each call
__device__ int      d_cntH[NOUT];
__device__ int2     d_entL[MAXSLOT * NOUT];   // slot-major {local col, val-bits}
__device__ int2     d_entH[MAXSLOT * NOUT];
__device__ unsigned d_done;

// ---------------- ELL fill, bucketed by column half ----------------
__global__ void k_fill(const int* __restrict__ rows,
                       const int* __restrict__ cols,
                       const float* __restrict__ vals) {
    int k = blockIdx.x * blockDim.x + threadIdx.x;
    if (k < NNZ) {
        int r = rows[k];
        int c = cols[k];
        int vb = __float_as_int(vals[k]);
        if (c < HALF) {
            int slot = atomicAdd(&d_cntL[r], 1);
            if (slot < MAXSLOT) d_entL[slot * NOUT + r] = make_int2(c, vb);
        } else {
            int slot = atomicAdd(&d_cntH[r], 1);
            if (slot < MAXSLOT) d_entH[slot * NOUT + r] = make_int2(c - HALF, vb);
        }
    }
}

// ---------------- Main SpMM kernel ----------------
// Round-8 structure (GPAIR=4, two column-half phases, 512 thr, 2 CTAs/SM)
// + ANTI-PHASE STAGGER: CTAs with (bid/148)&1 process halves in reverse
// order, so the two CTAs co-resident on an SM run opposite phases (one
// staging on DRAM while the other computes on L1). Accumulators persist
// across halves, so half order only permutes the FP sum (deterministic).
__global__ __launch_bounds__(THREADS, 2)
void k_main(const float* __restrict__ x, float* __restrict__ out) {
    extern __shared__ float4 sm4[];   // SMCOLS granules
    const int tid = threadIdx.x;
    const int pb  = blockIdx.x * GPAIR;
    const int h0  = (blockIdx.x / NSM) & 1;   // phase stagger

    float4 acc[ROWS_PT];
    #pragma unroll
    for (int i = 0; i < ROWS_PT; i++) acc[i] = make_float4(0.f, 0.f, 0.f, 0.f);

    #pragma unroll
    for (int hh = 0; hh < 2; hh++) {
        const int h = hh ^ h0;
        const int ncols = h ? (NIN - HALF) : HALF;
        const float* __restrict__ xh = x + (size_t)pb * NIN + h * HALF;

        // ---- stage this column half: 4 coalesced streams -> STS.128 ----
        #pragma unroll 2
        for (int j = tid; j < ncols; j += THREADS) {
            sm4[j] = make_float4(__ldg(xh + j),
                                 __ldg(xh + j + NIN),
                                 __ldg(xh + j + 2 * NIN),
                                 __ldg(xh + j + 3 * NIN));
        }
        __syncthreads();

        // ---- accumulate this half's entries: 6 lockstep row-chains ----
        const int*  __restrict__ cnt = h ? d_cntH : d_cntL;
        const int2* __restrict__ tbl = h ? d_entH : d_entL;

        int c[ROWS_PT];
        int cmax = 0;
        #pragma unroll
        for (int i = 0; i < ROWS_PT; i++) {
            int r = tid + i * THREADS;
            c[i] = (r < NOUT) ? min(cnt[r], MAXSLOT) : 0;
            cmax = max(cmax, c[i]);
        }

        for (int k = 0; k < cmax; k++) {
            const int2* __restrict__ ek = tbl + k * NOUT;
            #pragma unroll
            for (int i = 0; i < ROWS_PT; i++) {
                if (k < c[i]) {
                    int2 e = __ldg(ek + tid + i * THREADS);
                    float v  = __int_as_float(e.y);
                    float4 xv = sm4[e.x];
                    acc[i].x = fmaf(v, xv.x, acc[i].x);
                    acc[i].y = fmaf(v, xv.y, acc[i].y);
                    acc[i].z = fmaf(v, xv.z, acc[i].z);
                    acc[i].w = fmaf(v, xv.w, acc[i].w);
                }
            }
        }
        __syncthreads();   // smem reused by next half
    }

    // ---- coalesced stores: 4 output streams x 6 rows ----
    float* __restrict__ o0 = out + (size_t)pb * NOUT;
    #pragma unroll
    for (int i = 0; i < ROWS_PT; i++) {
        int r = tid + i * THREADS;
        if (r < NOUT) {
            o0[r]            = acc[i].x;
            o0[NOUT + r]     = acc[i].y;
            o0[2 * NOUT + r] = acc[i].z;
            o0[3 * NOUT + r] = acc[i].w;
        }
    }

    // ---- last finished block resets counts for the next graph replay ----
    __shared__ unsigned s_last;
    if (tid == 0) {
        __threadfence();
        s_last = (atomicAdd(&d_done, 1u) == (unsigned)(gridDim.x - 1));
    }
    __syncthreads();
    if (s_last) {
        for (int i = tid; i < NOUT; i += THREADS) { d_cntL[i] = 0; d_cntH[i] = 0; }
        if (tid == 0) d_done = 0;
    }
}

// ---------------- launch ----------------
extern "C" void kernel_launch(void* const* d_in, const int* in_sizes, int n_in,
                              void* d_out, int out_size) {
    const float* x      = (const float*)d_in[0];
    const int*   M_rows = (const int*)d_in[1];
    const int*   M_cols = (const int*)d_in[2];
    const float* M_vals = (const float*)d_in[3];
    float* out = (float*)d_out;

    (void)in_sizes; (void)n_in; (void)out_size;

    cudaFuncSetAttribute(k_main, cudaFuncAttributeMaxDynamicSharedMemorySize,
                         (int)SMEM_BYTES);

    k_fill<<<(NNZ + 255) / 256, 256>>>(M_rows, M_cols, M_vals);
    k_main<<<NBLK, THREADS, SMEM_BYTES>>>(x, out);
}

// round 15
// speedup vs baseline: 1.8570x; 1.1282x over previous
#include <cuda_runtime.h>
#include <cstdint>

// Problem constants (fixed shapes per reference)
#define NB      32
#define NC      64
#define NIN     10475
#define NOUT    2619
#define NNZ     (8 * NOUT)        // 20952
#define GPAIR   4                 // (b,c) pairs per block
#define NPAIR   (NB * NC)         // 2048
#define NBLK    (NPAIR / GPAIR)   // 512
#define THREADS 512
#define ROWS_PT 6                 // ceil(NOUT / THREADS)
#define MAXSLOT 32                // Poisson(4)/half-row; overflow ~0, guarded
#define HALF    5238              // column split point (ceil(NIN/2))
#define H1COLS  (NIN - HALF)      // 5237
#define H1LINES 164               // ceil(5237*4 / 128) lines per row, last within row
#define SMCOLS  5240              // padded float4 granules per half
#define SMEM_BYTES (SMCOLS * sizeof(float4))  // 83,840 B -> 2 CTAs/SM

// Device scratch (zero-init at load; no runtime allocation)
__device__ int      d_cntL[NOUT];             // per-half counts; reset each call
__device__ int      d_cntH[NOUT];
__device__ int2     d_entL[MAXSLOT * NOUT];   // slot-major {local col, val-bits}
__device__ int2     d_entH[MAXSLOT * NOUT];
__device__ unsigned d_done;

// ---------------- ELL fill, bucketed by column half ----------------
__global__ void k_fill(const int* __restrict__ rows,
                       const int* __restrict__ cols,
                       const float* __restrict__ vals) {
    int k = blockIdx.x * blockDim.x + threadIdx.x;
    if (k < NNZ) {
        int r = rows[k];
        int c = cols[k];
        int vb = __float_as_int(vals[k]);
        if (c < HALF) {
            int slot = atomicAdd(&d_cntL[r], 1);
            if (slot < MAXSLOT) d_entL[slot * NOUT + r] = make_int2(c, vb);
        } else {
            int slot = atomicAdd(&d_cntH[r], 1);
            if (slot < MAXSLOT) d_entH[slot * NOUT + r] = make_int2(c - HALF, vb);
        }
    }
}

// ---------------- Main SpMM kernel ----------------
// Round-8 structure (GPAIR=4, two column-half phases, 512 thr, 2 CTAs/SM,
// float4-interleaved gather: 1 LDS.128 per entry serves 4 pairs)
// + L2 PREFETCH: at the start of half-0 compute, each thread issues ~1.3
// prefetch.global.L2 lines covering this block's half-1 x data. The half-1
// DRAM reads stream during half-0 compute (when DRAM is otherwise idle) and
// half-1 staging becomes L2 hits. Prefetch has no reg writeback/scoreboard
// cost — only idle issue slots.
__global__ __launch_bounds__(THREADS, 2)
void k_main(const float* __restrict__ x, float* __restrict__ out) {
    extern __shared__ float4 sm4[];   // SMCOLS granules
    const int tid = threadIdx.x;
    const int pb  = blockIdx.x * GPAIR;

    float4 acc[ROWS_PT];
    #pragma unroll
    for (int i = 0; i < ROWS_PT; i++) acc[i] = make_float4(0.f, 0.f, 0.f, 0.f);

    #pragma unroll
    for (int h = 0; h < 2; h++) {
        const int ncols = h ? H1COLS : HALF;
        const float* __restrict__ xh = x + (size_t)pb * NIN + h * HALF;

        // ---- stage this column half: 4 coalesced streams -> STS.128 ----
        for (int j = tid; j < ncols; j += THREADS) {
            sm4[j] = make_float4(__ldg(xh + j),
                                 __ldg(xh + j + NIN),
                                 __ldg(xh + j + 2 * NIN),
                                 __ldg(xh + j + 3 * NIN));
        }
        __syncthreads();

        // ---- prefetch half 1 into L2 while computing half 0 ----
        if (h == 0) {
            const float* __restrict__ x1 = x + (size_t)pb * NIN + HALF;
            for (int l = tid; l < GPAIR * H1LINES; l += THREADS) {
                int row = l / H1LINES;
                int off = l - row * H1LINES;
                const float* p = x1 + (size_t)row * NIN + off * 32;
                asm volatile("prefetch.global.L2 [%0];" :: "l"(p));
            }
        }

        // ---- accumulate this half's entries: 6 lockstep row-chains ----
        const int*  __restrict__ cnt = h ? d_cntH : d_cntL;
        const int2* __restrict__ tbl = h ? d_entH : d_entL;

        int c[ROWS_PT];
        int cmax = 0;
        #pragma unroll
        for (int i = 0; i < ROWS_PT; i++) {
            int r = tid + i * THREADS;
            c[i] = (r < NOUT) ? min(cnt[r], MAXSLOT) : 0;
            cmax = max(cmax, c[i]);
        }

        for (int k = 0; k < cmax; k++) {
            const int2* __restrict__ ek = tbl + k * NOUT;
            #pragma unroll
            for (int i = 0; i < ROWS_PT; i++) {
                if (k < c[i]) {
                    int2 e = __ldg(ek + tid + i * THREADS);
                    float v  = __int_as_float(e.y);
                    float4 xv = sm4[e.x];
                    acc[i].x = fmaf(v, xv.x, acc[i].x);
                    acc[i].y = fmaf(v, xv.y, acc[i].y);
                    acc[i].z = fmaf(v, xv.z, acc[i].z);
                    acc[i].w = fmaf(v, xv.w, acc[i].w);
                }
            }
        }
        __syncthreads();   // smem reused by next half
    }

    // ---- coalesced stores: 4 output streams x 6 rows ----
    float* __restrict__ o0 = out + (size_t)pb * NOUT;
    #pragma unroll
    for (int i = 0; i < ROWS_PT; i++) {
        int r = tid + i * THREADS;
        if (r < NOUT) {
            o0[r]            = acc[i].x;
            o0[NOUT + r]     = acc[i].y;
            o0[2 * NOUT + r] = acc[i].z;
            o0[3 * NOUT + r] = acc[i].w;
        }
    }

    // ---- last finished block resets counts for the next graph replay ----
    __shared__ unsigned s_last;
    if (tid == 0) {
        __threadfence();
        s_last = (atomicAdd(&d_done, 1u) == (unsigned)(gridDim.x - 1));
    }
    __syncthreads();
    if (s_last) {
        for (int i = tid; i < NOUT; i += THREADS) { d_cntL[i] = 0; d_cntH[i] = 0; }
        if (tid == 0) d_done = 0;
    }
}

// ---------------- launch ----------------
extern "C" void kernel_launch(void* const* d_in, const int* in_sizes, int n_in,
                              void* d_out, int out_size) {
    const float* x      = (const float*)d_in[0];
    const int*   M_rows = (const int*)d_in[1];
    const int*   M_cols = (const int*)d_in[2];
    const float* M_vals = (const float*)d_in[3];
    float* out = (float*)d_out;

    (void)in_sizes; (void)n_in; (void)out_size;

    cudaFuncSetAttribute(k_main, cudaFuncAttributeMaxDynamicSharedMemorySize,
                         (int)SMEM_BYTES);

    k_fill<<<(NNZ + 255) / 256, 256>>>(M_rows, M_cols, M_vals);
    k_main<<<NBLK, THREADS, SMEM_BYTES>>>(x, out);
}